// round 16
// baseline (speedup 1.0000x reference)
#include <cuda_runtime.h>
#include <cuda_fp16.h>
#include <cstdint>

#define NB 4
#define NS 2048
#define NE 1024
#define ND 1024

// GEMM config: CTA 128x128, BK=64 fp16, 8 warps (2 M x 4 N), warp tile 64x32.
// 3 smem buffers, 2 cp.async groups in flight, 1 sync per K-iter.
constexpr int NTH = 256;
constexpr int TILE_B = 128 * 128;          // one fp16 tile: 128 rows x 128B
constexpr int STAGE_B = 2 * TILE_B;        // A + B
constexpr int NSTG = 3;
constexpr int DYN_SMEM = NSTG * STAGE_B;   // 96 KB

// fp16 operand scratch
__device__ __half g_xq[(size_t)NB * NS * NE];
__device__ __half g_xk[(size_t)NB * NS * NE];
__device__ __half g_xv[(size_t)NB * NS * NE];
__device__ __half g_wq[(size_t)ND * NE];
__device__ __half g_wk[(size_t)ND * NE];
__device__ __half g_wv[(size_t)ND * NE];
__device__ __half g_qh[(size_t)NB * NS * ND];
__device__ __half g_kh[(size_t)NB * NS * ND];
__device__ __half g_vt[(size_t)NB * ND * NS];   // V^T, written directly by projV
__device__ __half g_ph[(size_t)NB * NS * NS];   // unnormalized exp(score) fp16
__device__ float  g_ps[(size_t)NB * NS * 16 * 4]; // per (row, ctile, nwarp) partial sums
__device__ unsigned char g_mask[NB * NS];
__device__ int g_ntile[NB];                // leading non-masked 128-col tiles
__device__ int g_pvctr;                    // pv work-stealing counter

__device__ __forceinline__ uint32_t smem_u32(const void* p) {
    return (uint32_t)__cvta_generic_to_shared(p);
}
__device__ __forceinline__ void ldsm4(uint32_t addr, uint32_t* r) {
    asm volatile("ldmatrix.sync.aligned.m8n8.x4.shared.b16 {%0,%1,%2,%3}, [%4];"
        : "=r"(r[0]), "=r"(r[1]), "=r"(r[2]), "=r"(r[3]) : "r"(addr));
}
__device__ __forceinline__ void mma16816(float* c, const uint32_t* a, uint32_t b0, uint32_t b1) {
    asm volatile(
        "mma.sync.aligned.m16n8k16.row.col.f32.f16.f16.f32 "
        "{%0,%1,%2,%3}, {%4,%5,%6,%7}, {%8,%9}, {%0,%1,%2,%3};"
        : "+f"(c[0]), "+f"(c[1]), "+f"(c[2]), "+f"(c[3])
        : "r"(a[0]), "r"(a[1]), "r"(a[2]), "r"(a[3]), "r"(b0), "r"(b1));
}
__device__ __forceinline__ void cpa16(uint32_t dst, const void* src) {
    asm volatile("cp.async.cg.shared.global [%0], [%1], 16;" :: "r"(dst), "l"(src));
}
__device__ __forceinline__ void cpa_commit() {
    asm volatile("cp.async.commit_group;" ::: "memory");
}
template <int N> __device__ __forceinline__ void cpa_wait() {
    asm volatile("cp.async.wait_group %0;" :: "n"(N) : "memory");
}

// ---------------------------------------------------------------------------
// Core: acc += A[128 x kmax] * B[128 x kmax]^T, fp16 operands K-contiguous.
// Swizzle: 16B column c of row r lives at r*128 + ((c ^ (r&7))*16).
// ---------------------------------------------------------------------------
__device__ __forceinline__ void issue_stage(
    const __half* __restrict__ A, const __half* __restrict__ B,
    int lda, int ldb, int chunk, uint32_t sbase, int buf)
{
    const int tid = threadIdx.x;
    const __half* Ak = A + chunk * 64;
    const __half* Bk = B + chunk * 64;
    uint32_t sA = sbase + buf * STAGE_B;
    uint32_t sB = sA + TILE_B;
    #pragma unroll
    for (int t = 0; t < 4; t++) {
        int idx = tid + t * NTH;
        int r = idx >> 3, c = idx & 7;
        cpa16(sA + r * 128 + ((c ^ (r & 7)) << 4), Ak + (size_t)r * lda + c * 8);
    }
    #pragma unroll
    for (int t = 0; t < 4; t++) {
        int idx = tid + t * NTH;
        int r = idx >> 3, c = idx & 7;
        cpa16(sB + r * 128 + ((c ^ (r & 7)) << 4), Bk + (size_t)r * ldb + c * 8);
    }
    cpa_commit();
}

__device__ __forceinline__ void gemm_fp16(
    const __half* __restrict__ A, const __half* __restrict__ B,
    int lda, int ldb, int kmax, float acc[4][4][4], char* sm)
{
    const int tid = threadIdx.x;
    const int lane = tid & 31, wid = tid >> 5;
    const int wm = (wid >> 2) * 64;      // warp M offset (2 warps along M)
    const int wn = (wid & 3) * 32;       // warp N offset (4 warps along N)
    const uint32_t sbase = smem_u32(sm);

    const int nch = kmax / 64;
    issue_stage(A, B, lda, ldb, 0, sbase, 0);
    if (nch > 1) issue_stage(A, B, lda, ldb, 1, sbase, 1);

    const int ar = lane & 15, ac = lane >> 4;
    const int br = (lane & 7) + ((lane >> 4) << 3), bc = (lane >> 3) & 1;

    int buf = 0;
    for (int it = 0; it < nch; it++) {
        if (it + 1 < nch) cpa_wait<1>(); else cpa_wait<0>();
        __syncthreads();
        if (it + 2 < nch) {
            int nb = buf + 2; if (nb >= NSTG) nb -= NSTG;
            issue_stage(A, B, lda, ldb, it + 2, sbase, nb);
        }
        uint32_t sA = sbase + buf * STAGE_B;
        uint32_t sB = sA + TILE_B;

        #pragma unroll
        for (int kk = 0; kk < 4; kk++) {
            uint32_t af[4][4], bf[2][4];
            #pragma unroll
            for (int mi = 0; mi < 4; mi++) {
                int row = wm + mi * 16 + ar;
                int c = kk * 2 + ac;
                ldsm4(sA + row * 128 + ((c ^ (row & 7)) << 4), af[mi]);
            }
            #pragma unroll
            for (int nj2 = 0; nj2 < 2; nj2++) {
                int row = wn + nj2 * 16 + br;
                int c = kk * 2 + bc;
                ldsm4(sB + row * 128 + ((c ^ (row & 7)) << 4), bf[nj2]);
            }
            #pragma unroll
            for (int mi = 0; mi < 4; mi++)
                #pragma unroll
                for (int nj2 = 0; nj2 < 2; nj2++)
                    #pragma unroll
                    for (int j = 0; j < 2; j++)
                        mma16816(acc[mi][nj2 * 2 + j], af[mi],
                                 bf[nj2][2 * j], bf[nj2][2 * j + 1]);
        }
        if (++buf >= NSTG) buf = 0;
    }
}

// Shared projection body: Y[rowBase:,colBase:] = X @ W^T + b, scaled (row-major).
__device__ __forceinline__ void proj_body(
    const __half* __restrict__ X, const __half* __restrict__ W,
    const float* __restrict__ bias, __half* __restrict__ Y,
    float scale, int rowBase, int colBase, char* sm)
{
    float acc[4][4][4] = {};
    gemm_fp16(X + (size_t)rowBase * NE, W + (size_t)colBase * NE, NE, NE, NE, acc, sm);

    const int lane = threadIdx.x & 31, wid = threadIdx.x >> 5;
    const int wm = (wid >> 2) * 64, wn = (wid & 3) * 32;
    #pragma unroll
    for (int mi = 0; mi < 4; mi++) {
        const int r0 = rowBase + wm + mi * 16 + (lane >> 2);
        #pragma unroll
        for (int nj = 0; nj < 4; nj++) {
            const int col = colBase + wn + nj * 8 + (lane & 3) * 2;
            const float b0 = bias[col], b1 = bias[col + 1];
            *reinterpret_cast<__half2*>(Y + (size_t)r0 * ND + col) =
                __floats2half2_rn((acc[mi][nj][0] + b0) * scale,
                                  (acc[mi][nj][1] + b1) * scale);
            *reinterpret_cast<__half2*>(Y + (size_t)(r0 + 8) * ND + col) =
                __floats2half2_rn((acc[mi][nj][2] + b0) * scale,
                                  (acc[mi][nj][3] + b1) * scale);
        }
    }
}

// V projection with fused transpose: writes g_vt[b][d][s] directly.
constexpr int TP = 136;   // transposed-stage pitch in halves (272B, 16B-mult)

__device__ __forceinline__ void projv_body(
    const float* __restrict__ bias, int rowBase, int colBase, char* sm, int b)
{
    float acc[4][4][4] = {};
    gemm_fp16(g_xv + (size_t)rowBase * NE, g_wv + (size_t)colBase * NE,
              NE, NE, NE, acc, sm);
    __syncthreads();                       // all warps done with cp.async bufs

    __half* st = reinterpret_cast<__half*>(sm);   // [128 cols][TP] transposed
    const int tid = threadIdx.x;
    const int lane = tid & 31, wid = tid >> 5;
    const int wm = (wid >> 2) * 64, wn = (wid & 3) * 32;
    #pragma unroll
    for (int mi = 0; mi < 4; mi++) {
        const int r0 = wm + mi * 16 + (lane >> 2);
        #pragma unroll
        for (int nj = 0; nj < 4; nj++) {
            const int c0 = wn + nj * 8 + (lane & 3) * 2;
            const float b0 = bias[colBase + c0], b1 = bias[colBase + c0 + 1];
            #pragma unroll
            for (int h = 0; h < 2; h++) {
                const int r = r0 + h * 8;
                st[(c0 + 0) * TP + r] = __float2half_rn(acc[mi][nj][h * 2 + 0] + b0);
                st[(c0 + 1) * TP + r] = __float2half_rn(acc[mi][nj][h * 2 + 1] + b1);
            }
        }
    }
    __syncthreads();

    // Coalesced write-out: thread t -> col c = t>>1, s-half = t&1 (64 halves).
    const int sLocal = rowBase & (NS - 1);          // batch-local s offset
    const int c = tid >> 1;
    const int half = tid & 1;
    const uint4* src = reinterpret_cast<const uint4*>(st + c * TP + half * 64);
    uint4* dst = reinterpret_cast<uint4*>(
        g_vt + ((size_t)b * ND + colBase + c) * NS + sLocal + half * 64);
    #pragma unroll
    for (int j = 0; j < 8; j++) dst[j] = src[j];
}

// ---------------------------------------------------------------------------
// Fused mask + fp32->fp16 conversion kernel (grid union).
// ---------------------------------------------------------------------------
__device__ __forceinline__ void cvt3(const float* s0, const float* s1, const float* s2,
                                     __half* d0, __half* d1, __half* d2, int i) {
    float4 v0 = *reinterpret_cast<const float4*>(s0 + i);
    float4 v1 = *reinterpret_cast<const float4*>(s1 + i);
    float4 v2 = *reinterpret_cast<const float4*>(s2 + i);
    *reinterpret_cast<__half2*>(d0 + i)     = __floats2half2_rn(v0.x, v0.y);
    *reinterpret_cast<__half2*>(d0 + i + 2) = __floats2half2_rn(v0.z, v0.w);
    *reinterpret_cast<__half2*>(d1 + i)     = __floats2half2_rn(v1.x, v1.y);
    *reinterpret_cast<__half2*>(d1 + i + 2) = __floats2half2_rn(v1.z, v1.w);
    *reinterpret_cast<__half2*>(d2 + i)     = __floats2half2_rn(v2.x, v2.y);
    *reinterpret_cast<__half2*>(d2 + i + 2) = __floats2half2_rn(v2.z, v2.w);
}

constexpr int NMASK_BLK = (NB * NS) / 256;          // 32
constexpr int NIN_BLK   = (NB * NS * NE) / 1024;    // 8192
constexpr int NW_BLK    = (ND * NE) / 1024;         // 1024

__global__ __launch_bounds__(256) void prep_fused_kernel(
    const void* __restrict__ pmv,
    const float* __restrict__ q, const float* __restrict__ k,
    const float* __restrict__ v,
    const float* __restrict__ Wq, const float* __restrict__ Wk,
    const float* __restrict__ Wv)
{
    const int bid = blockIdx.x;
    const int tid = threadIdx.x;
    if (bid < NMASK_BLK) {
        const unsigned int* pm = (const unsigned int*)pmv;
        __shared__ int found;
        if (tid == 0) found = 0;
        __syncthreads();
        for (int i = tid; i < 2048; i += 256) {
            unsigned int w = pm[i];
            if (w != 0u && w != 1u && w != 0x3f800000u) found = 1;
        }
        __syncthreads();
        const int mode = found;
        int idx = bid * 256 + tid;
        unsigned char m;
        if (mode) m = (((const unsigned char*)pmv)[idx] != 0) ? 1 : 0;
        else      m = (pm[idx] != 0u) ? 1 : 0;
        g_mask[idx] = m;
        if (bid == 0 && tid == 0) g_pvctr = 0;   // reset pv work counter
        if (bid == 0 && tid < NB) {
            int n = 0;
            #pragma unroll
            for (int t = 0; t < NS / 128; t++) {
                int j = tid * NS + t * 128;
                unsigned char mm;
                if (mode) mm = (((const unsigned char*)pmv)[j] != 0) ? 1 : 0;
                else      mm = (pm[j] != 0u) ? 1 : 0;
                if (mm == 0) n++;
            }
            g_ntile[tid] = n;
        }
    } else if (bid < NMASK_BLK + NIN_BLK) {
        int i = ((bid - NMASK_BLK) * 256 + tid) * 4;
        cvt3(q, k, v, g_xq, g_xk, g_xv, i);
    } else {
        int i = ((bid - NMASK_BLK - NIN_BLK) * 256 + tid) * 4;
        cvt3(Wq, Wk, Wv, g_wq, g_wk, g_wv, i);
    }
}

// ---------------------------------------------------------------------------
// Kernel 1: Q and K projections (z: 0=Q pre-scaled by 1/32, 1=K).
// ---------------------------------------------------------------------------
__global__ __launch_bounds__(NTH, 2) void proj_qk_kernel(
    const float* __restrict__ bq, const float* __restrict__ bk)
{
    extern __shared__ char sm[];
    const int which = blockIdx.z;
    const int rowBase = blockIdx.y * 128;
    const int colBase = blockIdx.x * 128;

    if (which == 1) {   // K: skip rows no consumer reads
        const int b = rowBase >> 11;
        if ((rowBase & (NS - 1)) >= (g_ntile[b] << 7)) return;
    }
    if (which == 0)
        proj_body(g_xq, g_wq, bq, g_qh, 0.03125f, rowBase, colBase, sm);
    else
        proj_body(g_xk, g_wk, bk, g_kh, 1.0f, rowBase, colBase, sm);
}

// ---------------------------------------------------------------------------
// Kernel 2 (grid union): qk exp-score tiles [0, 544) + transposed V projection.
// ---------------------------------------------------------------------------
constexpr int NTRI = (NS / 128) * ((NS / 128) + 1) / 2;   // 136
constexpr int QK_BLKS = NTRI * NB;                        // 544
constexpr int PV_PROJ_BLKS = (ND / 128) * ((NB * NS) / 128);  // 512

__global__ __launch_bounds__(NTH, 2) void qk_projv_kernel(const float* __restrict__ bv)
{
    extern __shared__ char sm[];
    const int bid = blockIdx.x;

    if (bid >= QK_BLKS) {
        // ---- V projection (fused transpose into g_vt) ----
        const int i = bid - QK_BLKS;
        const int colBase = (i & 7) * 128;
        const int rowBase = (i >> 3) * 128;
        const int b = rowBase >> 11;
        if ((rowBase & (NS - 1)) >= (g_ntile[b] << 7)) return;   // dead V rows
        projv_body(bv, rowBase, colBase, sm, b);
        return;
    }

    // ---- qk exp-score tile ----
    const int b = bid / NTRI;
    int t = bid - b * NTRI;
    int rt = (int)((sqrtf(8.0f * (float)t + 1.0f) - 1.0f) * 0.5f);
    while ((rt + 1) * (rt + 2) / 2 <= t) rt++;
    while (rt * (rt + 1) / 2 > t) rt--;
    const int ct = t - rt * (rt + 1) / 2;
    const int rowBase = rt * 128;
    const int colBase = ct * 128;

    if (ct >= g_ntile[b]) return;   // fully-masked column tile

    float acc[4][4][4] = {};
    const __half* Q = g_qh + (size_t)b * NS * ND + (size_t)rowBase * ND;
    const __half* K = g_kh + (size_t)b * NS * ND + (size_t)colBase * ND;
    gemm_fp16(Q, K, ND, ND, ND, acc, sm);

    __half* op = g_ph + (size_t)b * NS * NS;
    const int lane = threadIdx.x & 31, wid = threadIdx.x >> 5;
    const int wm = (wid >> 2) * 64, wn = (wid & 3) * 32;
    #pragma unroll
    for (int mi = 0; mi < 4; mi++) {
        #pragma unroll
        for (int h = 0; h < 2; h++) {
            const int row = rowBase + wm + mi * 16 + (lane >> 2) + h * 8;
            float rs = 0.0f;
            #pragma unroll
            for (int nj = 0; nj < 4; nj++) {
                const int col = colBase + wn + nj * 8 + (lane & 3) * 2;
                float v0 = acc[mi][nj][h * 2 + 0];
                float v1 = acc[mi][nj][h * 2 + 1];
                v0 = (col > row     || g_mask[b * NS + col])     ? 0.0f : __expf(v0);
                v1 = (col + 1 > row || g_mask[b * NS + col + 1]) ? 0.0f : __expf(v1);
                *reinterpret_cast<__half2*>(op + (size_t)row * NS + col) =
                    __floats2half2_rn(v0, v1);
                rs += v0 + v1;
            }
            rs += __shfl_xor_sync(0xffffffffu, rs, 1);
            rs += __shfl_xor_sync(0xffffffffu, rs, 2);
            if ((lane & 3) == 0)
                g_ps[(((size_t)(b * NS + row)) << 6) + (ct << 2) + (wid & 3)] = rs;
        }
    }
}

// ---------------------------------------------------------------------------
// Kernel 4: O = (E @ V) * inv[row] (via VT), work-stealing over 512 tiles.
// Exactly 296 CTAs (2/SM x 148) pull heavy-first tiles from a global counter:
// per-SM load balances automatically. Tile->output map is fixed and writes
// are disjoint, so output is deterministic despite the atomic.
// ---------------------------------------------------------------------------
__device__ __forceinline__ void pv_tile(
    float* __restrict__ outp, int b, int rowBase, int colBase,
    char* sm, float* s_inv)
{
    int kmax = rowBase + 128;
    const int lend = g_ntile[b] << 7;
    if (lend < kmax) kmax = lend;

    float acc[4][4][4] = {};
    const __half* P  = g_ph + (size_t)b * NS * NS + (size_t)rowBase * NS;
    const __half* VT = g_vt + (size_t)b * ND * NS + (size_t)colBase * NS;
    gemm_fp16(P, VT, NS, NS, kmax, acc, sm);

    const int tid = threadIdx.x;
    const int nt = kmax >> 7;              // 1..16
    if (tid < 128) {
        const float4* ps4 = reinterpret_cast<const float4*>(
            g_ps + (((size_t)(b * NS + rowBase + tid)) << 6));
        float sum = 0.0f;
        for (int j = 0; j < nt; j++) {
            float4 p = ps4[j];
            sum += (p.x + p.y) + (p.z + p.w);
        }
        s_inv[tid] = 1.0f / sum;
    }
    __syncthreads();

    float* O = outp + (size_t)b * NS * ND;
    const int lane = tid & 31, wid = tid >> 5;
    const int wm = (wid >> 2) * 64, wn = (wid & 3) * 32;
    #pragma unroll
    for (int mi = 0; mi < 4; mi++) {
        const int rl = wm + mi * 16 + (lane >> 2);
        const int r0 = rowBase + rl;
        const float inv0 = s_inv[rl];
        const float inv1 = s_inv[rl + 8];
        #pragma unroll
        for (int nj = 0; nj < 4; nj++) {
            const int col = colBase + wn + nj * 8 + (lane & 3) * 2;
            *reinterpret_cast<float2*>(O + (size_t)r0 * ND + col) =
                make_float2(acc[mi][nj][0] * inv0, acc[mi][nj][1] * inv0);
            *reinterpret_cast<float2*>(O + (size_t)(r0 + 8) * ND + col) =
                make_float2(acc[mi][nj][2] * inv1, acc[mi][nj][3] * inv1);
        }
    }
}

constexpr int PV_TILES = 16 * 8 * NB;       // 512
constexpr int PV_CTAS  = 296;               // 2 per SM x 148 SMs

__global__ __launch_bounds__(NTH, 2) void pv_mma_kernel(float* __restrict__ outp)
{
    extern __shared__ char sm[];
    __shared__ float s_inv[128];
    __shared__ int s_t;

    for (;;) {
        if (threadIdx.x == 0) s_t = atomicAdd(&g_pvctr, 1);
        __syncthreads();
        const int t = s_t;
        if (t >= PV_TILES) return;
        // heavy-first: rt descends with t
        const int rt = 15 - (t >> 5);
        const int rest = t & 31;
        const int colBase = (rest & 7) * 128;
        const int b = rest >> 3;
        pv_tile(outp, b, rt * 128, colBase, sm, s_inv);
        __syncthreads();   // all epilogue reads of s_inv/s_t done before reuse
    }
}

// ---------------------------------------------------------------------------
// Launch (4 kernels)
// ---------------------------------------------------------------------------
extern "C" void kernel_launch(void* const* d_in, const int* in_sizes, int n_in,
                              void* d_out, int out_size)
{
    const float* q  = (const float*)d_in[0];
    const float* k  = (const float*)d_in[1];
    const float* v  = (const float*)d_in[2];
    const float* Wq = (const float*)d_in[3];
    const float* bq = (const float*)d_in[4];
    const float* Wk = (const float*)d_in[5];
    const float* bk = (const float*)d_in[6];
    const float* Wv = (const float*)d_in[7];
    const float* bv = (const float*)d_in[8];
    const void*  pm = d_in[9];

    cudaFuncSetAttribute(proj_qk_kernel,  cudaFuncAttributeMaxDynamicSharedMemorySize, DYN_SMEM);
    cudaFuncSetAttribute(qk_projv_kernel, cudaFuncAttributeMaxDynamicSharedMemorySize, DYN_SMEM);
    cudaFuncSetAttribute(pv_mma_kernel,   cudaFuncAttributeMaxDynamicSharedMemorySize, DYN_SMEM);

    prep_fused_kernel<<<NMASK_BLK + NIN_BLK + NW_BLK, 256>>>(pm, q, k, v, Wq, Wk, Wv);

    proj_qk_kernel<<<dim3(ND / 128, (NB * NS) / 128, 2), NTH, DYN_SMEM>>>(bq, bk);

    qk_projv_kernel<<<QK_BLKS + PV_PROJ_BLKS, NTH, DYN_SMEM>>>(bv);

    pv_mma_kernel<<<PV_CTAS, NTH, DYN_SMEM>>>((float*)d_out);
}